// round 16
// baseline (speedup 1.0000x reference)
#include <cuda_runtime.h>
#include <cuda_fp16.h>
#include <math.h>
#include <stdint.h>

// ---------------- problem constants ----------------------------------------
#define B_    1024
#define DIM_  512
#define C_    1000
#define N_    8
#define CN_   8000
#define CNP_  8064
#define NEED_ 392
#define WLAMBDA 0.3
#define KS32  32        // K / 16
#define NTILES 1008
#define GRID_G 444
#define EPI_BLOCKS (B_ + (CN_ + 255) / 256)   // 1056

// ---------------- scratch -----------------------------------------------------
__device__ uint4    g_xrA[(size_t)(B_ / 16) * KS32 * 32];
__device__ uint4    g_pTA[(size_t)(CNP_ / 16) * KS32 * 32];
__device__ uint4    g_pTB[(size_t)(CNP_ / 16) * KS32 * 32];
__device__ uint4    g_ccB[(size_t)64 * KS32 * 32];
__device__ uint32_t g_simh[(size_t)B_ * (CN_ / 2)];   // fp16x2 sim
__device__ float    g_sinv[CNP_];
__device__ float    g_pmax[CN_ * 8];
__device__ float    g_psum[CN_ * 8];
__device__ float    g_diag[CN_];
__device__ double   g_acc[2];
__device__ unsigned g_done;

// ---------------- helpers ----------------------------------------------------
__device__ __forceinline__ uint32_t h2u(float a, float b) {
    __half2 h = __floats2half2_rn(a, b);
    return *(uint32_t*)&h;
}
__device__ __forceinline__ uint32_t smem_u32(const void* p) {
    uint32_t a;
    asm("{ .reg .u64 t; cvta.to.shared.u64 t, %1; cvt.u32.u64 %0, t; }" : "=r"(a) : "l"(p));
    return a;
}
__device__ __forceinline__ void cpa16(uint32_t dst, const void* src) {
    uint64_t g = __cvta_generic_to_global(src);
    asm volatile("cp.async.cg.shared.global [%0], [%1], 16;" :: "r"(dst), "l"(g));
}
#define CP_COMMIT() asm volatile("cp.async.commit_group;" ::: "memory")

__device__ __forceinline__ void mma_f16(float* c, const uint4& a, uint32_t b0, uint32_t b1) {
    asm volatile(
        "mma.sync.aligned.m16n8k16.row.col.f32.f16.f16.f32 "
        "{%0,%1,%2,%3}, {%4,%5,%6,%7}, {%8,%9}, {%0,%1,%2,%3};"
        : "+f"(c[0]), "+f"(c[1]), "+f"(c[2]), "+f"(c[3])
        : "r"(a.x), "r"(a.y), "r"(a.z), "r"(a.w), "r"(b0), "r"(b1));
}
__device__ __forceinline__ uint32_t key2_of(uint32_t w) {
    uint32_t s = (w & 0x80008000u) >> 15;
    uint32_t m = s * 0x7FFFu + 0x80008000u;
    return w ^ m;
}
__device__ __forceinline__ float val16(unsigned k) {
    unsigned short h = (k & 0x8000u) ? (unsigned short)(k ^ 0x8000u) : (unsigned short)(~k);
    return __half2float(__ushort_as_half(h));
}

// ---------------- prep 1: column inverse norms -------------------------------
__global__ void __launch_bounds__(256) colnorm_kernel(const float* __restrict__ proxies) {
    __shared__ float red[256];
    int tid = threadIdx.x;
    if (blockIdx.x == 0) {
        if (tid < 2) g_acc[tid] = 0.0;
        if (tid == 2) g_done = 0u;
    }
    int col = tid & 31, part = tid >> 5;
    int j = blockIdx.x * 32 + col;
    float acc = 0.f;
    if (j < CN_) {
        int d0 = part * 64;
        #pragma unroll 8
        for (int d = d0; d < d0 + 64; d++) {
            float v = proxies[(size_t)d * CN_ + j];
            acc += v * v;
        }
    }
    red[tid] = acc;
    __syncthreads();
    if (tid < 32) {
        float s = 0.f;
        #pragma unroll
        for (int p = 0; p < 8; p++) s += red[p * 32 + tid];
        g_sinv[j] = (j < CN_) ? (1.0f / fmaxf(sqrtf(s), 1e-12f)) : 0.f;
    }
}

// ---------------- prep 2: fragment emission (568 blocks) ----------------------
__global__ void __launch_bounds__(256) prep_frag(const float* __restrict__ x,
                                                 const float* __restrict__ proxies) {
    __shared__ __align__(16) char buf[34304];
    int tid = threadIdx.x;

    if (blockIdx.x >= 504) {
        int G = blockIdx.x - 504;
        float (*xs)[520] = (float(*)[520])buf;
        const float4* x4 = (const float4*)x;
        #pragma unroll
        for (int e = 0; e < 8; e++) {
            int lin = e * 256 + tid;
            int row = lin >> 7, kf = lin & 127;
            float4 v = x4[(size_t)(G * 16 + row) * 128 + kf];
            xs[row][kf * 4 + 0] = v.x; xs[row][kf * 4 + 1] = v.y;
            xs[row][kf * 4 + 2] = v.z; xs[row][kf * 4 + 3] = v.w;
        }
        __syncthreads();
        #pragma unroll
        for (int e = 0; e < 4; e++) {
            int lin = e * 256 + tid;
            int ks = lin >> 5, q = (lin >> 2) & 7, lc = lin & 3;
            int k0 = ks * 16 + lc * 2;
            uint4 o;
            o.x = h2u(xs[q][k0],     xs[q][k0 + 1]);
            o.y = h2u(xs[q + 8][k0], xs[q + 8][k0 + 1]);
            o.z = h2u(xs[q][k0 + 8], xs[q][k0 + 9]);
            o.w = h2u(xs[q + 8][k0 + 8], xs[q + 8][k0 + 9]);
            g_xrA[((size_t)G * KS32 + ks) * 32 + q * 4 + lc] = o;
        }
        return;
    }

    int jb = blockIdx.x >> 3, chunk = blockIdx.x & 7;
    int j0 = jb * 128, dbase = chunk * 64;
    float (*xs)[132] = (float(*)[132])buf;
    float* sinv = (float*)(buf + 33792);

    if (tid < 128) sinv[tid] = g_sinv[j0 + tid];

    #pragma unroll 4
    for (int e = 0; e < 32; e++) {
        int lin = e * 256 + tid;
        int d = lin >> 7, jj = lin & 127;
        int j = j0 + jj;
        xs[d][jj] = (j < CN_) ? proxies[(size_t)(dbase + d) * CN_ + j] : 0.f;
    }
    __syncthreads();

    #pragma unroll
    for (int e = 0; e < 4; e++) {
        int lin = e * 256 + tid;
        int g = lin >> 7, ksl = (lin >> 5) & 3, q = (lin >> 2) & 7, lc = lin & 3;
        int r0 = g * 16 + q, r1 = r0 + 8;
        float iv0 = sinv[r0], iv1 = sinv[r1];
        int dl = ksl * 16 + lc * 2;
        float v00 = xs[dl][r0] * iv0,     v01 = xs[dl + 1][r0] * iv0;
        float v10 = xs[dl][r1] * iv1,     v11 = xs[dl + 1][r1] * iv1;
        float v08 = xs[dl + 8][r0] * iv0, v09 = xs[dl + 9][r0] * iv0;
        float v18 = xs[dl + 8][r1] * iv1, v19 = xs[dl + 9][r1] * iv1;
        size_t idx = ((size_t)(j0 / 16 + g) * KS32 + chunk * 4 + ksl) * 32 + q * 4 + lc;
        uint4 oa, ob;
        oa.x = h2u(v00, v01); oa.y = h2u(v10, v11);
        oa.z = h2u(v08, v09); oa.w = h2u(v18, v19);
        ob.x = h2u(v00, v01); ob.y = h2u(v08, v09);
        ob.z = h2u(v10, v11); ob.w = h2u(v18, v19);
        g_pTA[idx] = oa;
        g_pTB[idx] = ob;
    }

    if (tid < 128) {
        int ksl = tid >> 5, qB = (tid >> 2) & 7, lc = tid & 3;
        int ca = jb * 16 + qB, cb = ca + 8;
        int dl = ksl * 16 + lc * 2;
        float a0 = 0.f, a1 = 0.f, a8 = 0.f, a9 = 0.f;
        float b0 = 0.f, b1 = 0.f, b8 = 0.f, b9 = 0.f;
        if (ca < C_) {
            #pragma unroll
            for (int n = 0; n < 8; n++) {
                int jl = qB * 8 + n;
                float iv = sinv[jl];
                a0 += xs[dl][jl] * iv;     a1 += xs[dl + 1][jl] * iv;
                a8 += xs[dl + 8][jl] * iv; a9 += xs[dl + 9][jl] * iv;
            }
        }
        if (cb < C_) {
            #pragma unroll
            for (int n = 0; n < 8; n++) {
                int jl = 64 + qB * 8 + n;
                float iv = sinv[jl];
                b0 += xs[dl][jl] * iv;     b1 += xs[dl + 1][jl] * iv;
                b8 += xs[dl + 8][jl] * iv; b9 += xs[dl + 9][jl] * iv;
            }
        }
        uint4 o;
        o.x = h2u(a0, a1);
        o.y = h2u(a8, a9);
        o.z = h2u(b0, b1);
        o.w = h2u(b8, b9);
        g_ccB[((size_t)jb * KS32 + chunk * 4 + ksl) * 32 + qB * 4 + lc] = o;
    }
}

// ---------------- 2-stage fp16 GEMM, 3 CTAs/SM (grid 444, <=3 tiles/CTA) -----
#define NCHUNK 8
#define STG 32768
#define DYN_SMEM (2 * STG)   // 65536
#define TP 128               // 128x128 floats = 65536 B exactly; float2-aligned

__device__ __forceinline__ void tile_coords(int bid, const uint4*& Ag, const uint4*& Bg,
                                            int& bm, int& bn, bool& mode1) {
    mode1 = (bid >= 504);
    if (!mode1) {
        Ag = g_xrA; Bg = g_pTB;
        bn = (bid % 63) * 128; bm = (bid / 63) * 128;
    } else {
        int b2 = bid - 504;
        Ag = g_pTA; Bg = g_ccB;
        bn = (b2 & 7) * 128; bm = (b2 >> 3) * 128;
    }
}

__device__ __forceinline__ void load_stage_g(uint32_t sb, int tid, const uint4* Ag,
                                             const uint4* Bg, int GA0, int GB0,
                                             int ch, int s) {
    uint32_t stage = sb + (uint32_t)s * STG;
    #pragma unroll
    for (int e = 0; e < 8; e++) {
        int lin = e * 256 + tid;
        if (lin < 1024) {
            int ks = lin >> 8, g = (lin >> 5) & 7, q = (lin >> 2) & 7, lc = lin & 3;
            cpa16(stage + (uint32_t)lin * 16,
                  Ag + ((size_t)(GA0 + g) * KS32 + ch * 4 + ks) * 32 + q * 4 + lc);
        } else {
            int l2 = lin - 1024;
            int ks = l2 >> 8, gB = (l2 >> 5) & 7, qB = (l2 >> 2) & 7, lc = l2 & 3;
            cpa16(stage + 16384u + (uint32_t)l2 * 16,
                  Bg + ((size_t)(GB0 + gB) * KS32 + ch * 4 + ks) * 32 + qB * 4 + lc);
        }
    }
    CP_COMMIT();
}

__global__ void __launch_bounds__(256, 3) gemm_all() {
    extern __shared__ char sh[];
    int tid = threadIdx.x, wid = tid >> 5, lane = tid & 31;
    int lr = lane >> 2, lc4 = lane & 3;
    uint32_t sb = smem_u32(sh);
    int ga = (wid >> 2) * 4;
    int gb2 = (wid & 3) * 2;
    int wm = (wid >> 2) * 64, wn = (wid & 3) * 32;
    bool preloaded = false;

    for (int t = 0; t < 3; t++) {
        int bid = (int)blockIdx.x + t * GRID_G;
        if (bid >= NTILES) break;

        const uint4 *Ag, *Bg;
        int bm, bn;
        bool mode1;
        tile_coords(bid, Ag, Bg, bm, bn, mode1);
        int GA0 = bm / 16, GB0 = bn / 16;

        if (!preloaded) load_stage_g(sb, tid, Ag, Bg, GA0, GB0, 0, 0);

        float c[4][4][4];
        #pragma unroll
        for (int mt = 0; mt < 4; mt++)
            #pragma unroll
            for (int nt = 0; nt < 4; nt++)
                #pragma unroll
                for (int i = 0; i < 4; i++) c[mt][nt][i] = 0.f;

        for (int ch = 0; ch < NCHUNK; ch++) {
            asm volatile("cp.async.wait_group 0;" ::: "memory");   // chunk ch arrived
            __syncthreads();                                       // all compute on ch-1 done

            if (ch + 1 < NCHUNK) load_stage_g(sb, tid, Ag, Bg, GA0, GB0, ch + 1, (ch + 1) & 1);

            const uint4* As = (const uint4*)(sh + (ch & 1) * STG);
            const uint4* Bs = (const uint4*)(sh + (ch & 1) * STG + 16384);

            #pragma unroll
            for (int ks = 0; ks < 4; ks++) {
                uint4 va[4], vb[2];
                #pragma unroll
                for (int mt = 0; mt < 4; mt++)
                    va[mt] = As[((ks * 8 + ga + mt) * 8 + lr) * 4 + lc4];
                #pragma unroll
                for (int u = 0; u < 2; u++)
                    vb[u] = Bs[((ks * 8 + gb2 + u) * 8 + lr) * 4 + lc4];
                #pragma unroll
                for (int mt = 0; mt < 4; mt++) {
                    mma_f16(c[mt][0], va[mt], vb[0].x, vb[0].y);
                    mma_f16(c[mt][1], va[mt], vb[0].z, vb[0].w);
                    mma_f16(c[mt][2], va[mt], vb[1].x, vb[1].y);
                    mma_f16(c[mt][3], va[mt], vb[1].z, vb[1].w);
                }
            }
        }
        __syncthreads();   // all MMAs done; both buffers free

        preloaded = false;
        if (!mode1) {
            int nbid = (int)blockIdx.x + (t + 1) * GRID_G;
            if (nbid < NTILES) {
                const uint4 *Ag2, *Bg2;
                int bm2, bn2;
                bool m1n;
                tile_coords(nbid, Ag2, Bg2, bm2, bn2, m1n);
                load_stage_g(sb, tid, Ag2, Bg2, bm2 / 16, bn2 / 16, 0, 0);
                preloaded = true;
            }
            #pragma unroll
            for (int mt = 0; mt < 4; mt++) {
                int row = bm + wm + mt * 16 + lr;
                #pragma unroll
                for (int nt = 0; nt < 4; nt++) {
                    int col = bn + wn + nt * 8 + lc4 * 2;
                    if (col < CN_) {
                        g_simh[(size_t)row * (CN_ / 2) + (col >> 1)] = h2u(c[mt][nt][0], c[mt][nt][1]);
                        g_simh[(size_t)(row + 8) * (CN_ / 2) + (col >> 1)] = h2u(c[mt][nt][2], c[mt][nt][3]);
                    }
                }
            }
            continue;
        }

        // mode 1: smem tile dump (128 x 128 floats = 64KB) + row lse partials
        float* tile = (float*)sh;
        #pragma unroll
        for (int mt = 0; mt < 4; mt++) {
            int r0 = wm + mt * 16 + lr;
            #pragma unroll
            for (int nt = 0; nt < 4; nt++) {
                int cc = wn + nt * 8 + lc4 * 2;
                *(float2*)&tile[r0 * TP + cc] = make_float2(c[mt][nt][0], c[mt][nt][1]);
                *(float2*)&tile[(r0 + 8) * TP + cc] = make_float2(c[mt][nt][2], c[mt][nt][3]);
            }
        }
        __syncthreads();

        {
            int r = tid >> 1, h = tid & 1;
            int gr = bm + r;
            int vcols = C_ - bn; if (vcols > 128) vcols = 128;
            int cA = h * 64;
            int nc = vcols - cA; if (nc > 64) nc = 64; if (nc < 0) nc = 0;
            int rot = (2 * r) & 63;   // per-row rotation: conflict degree 2 instead of 32
            float m = -3.0e38f;
            for (int j = 0; j < nc; j++) {
                int col = cA + ((j + rot) & 63);
                if (col < vcols) m = fmaxf(m, tile[r * TP + col]);
            }
            float s = 0.f;
            for (int j = 0; j < nc; j++) {
                int col = cA + ((j + rot) & 63);
                if (col < vcols) s += __expf(tile[r * TP + col] - m);
            }
            float mo = __shfl_xor_sync(0xffffffffu, m, 1);
            float so = __shfl_xor_sync(0xffffffffu, s, 1);
            float M = fmaxf(m, mo);
            float S = s * __expf(m - M) + so * __expf(mo - M);
            if (h == 0 && gr < CN_) {
                g_pmax[gr * 8 + (bn >> 7)] = M;
                g_psum[gr * 8 + (bn >> 7)] = S;
                int cl = gr >> 3;
                if (cl >= bn && cl - bn < vcols) g_diag[gr] = tile[r * TP + (cl - bn)];
            }
        }
        __syncthreads();
    }
}

// ---------------- epilogue: topk+loss, lse combine, inline finalize ----------
__global__ void __launch_bounds__(256) epilogue_kernel(const int* __restrict__ target,
                                                       float* out, int out_size) {
    __shared__ unsigned short key16[CN_];
    __shared__ unsigned hist[1024];
    __shared__ float    cls[C_];
    __shared__ unsigned uns[8];
    __shared__ float    wsum[8];
    __shared__ float    s_pos;
    __shared__ unsigned sh_bin, sh_need;

    int tid = threadIdx.x;
    int wid = tid >> 5, lane = tid & 31;

    if (blockIdx.x >= B_) {
        int row = (int)(blockIdx.x - B_) * 256 + tid;
        float regv = 0.f;
        if (row < CN_) {
            float M = -3.0e38f;
            #pragma unroll
            for (int t = 0; t < 8; t++) M = fmaxf(M, g_pmax[row * 8 + t]);
            float S = 0.f;
            #pragma unroll
            for (int t = 0; t < 8; t++)
                S += g_psum[row * 8 + t] * __expf(g_pmax[row * 8 + t] - M);
            regv = M + __logf(S) - g_diag[row];
        }
        #pragma unroll
        for (int o = 16; o > 0; o >>= 1) regv += __shfl_xor_sync(0xffffffffu, regv, o);
        if (lane == 0 && regv != 0.f) atomicAdd(&g_acc[1], (double)regv);
        __syncthreads();
        goto completion;
    }

    {
    int b = blockIdx.x;
    int tgt = target[b];
    const uint4* rowh = (const uint4*)(g_simh + (size_t)b * (CN_ / 2));
    uint32_t* k32 = (uint32_t*)key16;

    for (int i = tid; i < 1024; i += 256) hist[i] = 0;
    if (tid == 0) s_pos = 0.f;
    __syncthreads();

    float pos = 0.f;
    for (int g = tid; g < C_; g += 256) {
        uint4 w = rowh[g];
        if (g == tgt) {
            float2 f0 = __half22float2(*(__half2*)&w.x);
            float2 f1 = __half22float2(*(__half2*)&w.y);
            float2 f2 = __half22float2(*(__half2*)&w.z);
            float2 f3 = __half22float2(*(__half2*)&w.w);
            pos = f0.x + f0.y + f1.x + f1.y + f2.x + f2.y + f3.x + f3.y;
            *(uint4*)&k32[g * 4] = make_uint4(0, 0, 0, 0);
        } else {
            uint32_t k0 = key2_of(w.x), k1 = key2_of(w.y), k2 = key2_of(w.z), k3 = key2_of(w.w);
            *(uint4*)&k32[g * 4] = make_uint4(k0, k1, k2, k3);
            atomicAdd(&hist[(k0 & 0xFFFFu) >> 6], 1u);
            atomicAdd(&hist[k0 >> 22], 1u);
            atomicAdd(&hist[(k1 & 0xFFFFu) >> 6], 1u);
            atomicAdd(&hist[k1 >> 22], 1u);
            atomicAdd(&hist[(k2 & 0xFFFFu) >> 6], 1u);
            atomicAdd(&hist[k2 >> 22], 1u);
            atomicAdd(&hist[(k3 & 0xFFFFu) >> 6], 1u);
            atomicAdd(&hist[k3 >> 22], 1u);
        }
    }
    if (pos != 0.f) atomicAdd(&s_pos, pos);
    __syncthreads();

    auto select_bin = [&](int nb, unsigned nd) {
        int nch = nb >> 3;
        unsigned chunk = 0;
        if (tid < nch) {
            int base = tid * 8;
            #pragma unroll
            for (int i = 0; i < 8; i++) chunk += hist[base + i];
        }
        unsigned v = chunk;
        #pragma unroll
        for (int off = 1; off < 32; off <<= 1) {
            unsigned t = __shfl_down_sync(0xffffffffu, v, off);
            if (lane + off < 32) v += t;
        }
        if (lane == 0) uns[wid] = v;
        __syncthreads();
        unsigned woff = 0;
        for (int w = wid + 1; w < 8; w++) woff += uns[w];
        unsigned Sincl = v + woff;
        unsigned Saft = Sincl - chunk;
        if (tid < nch && Saft < nd && Sincl >= nd) {
            unsigned cum = Saft;
            int bb = tid * 8 + 7;
            while (cum + hist[bb] < nd) { cum += hist[bb]; bb--; }
            sh_bin = (unsigned)bb;
            sh_need = nd - cum;
        }
        __syncthreads();
    };

    select_bin(1024, NEED_);
    unsigned p10 = sh_bin;
    unsigned need = sh_need;
    __syncthreads();

    for (int i = tid; i < 64; i += 256) hist[i] = 0;
    __syncthreads();
    for (int t = tid; t < CN_ / 2; t += 256) {
        uint32_t w = k32[t];
        unsigned a = w & 0xFFFFu, bq = w >> 16;
        if ((a >> 6) == p10) atomicAdd(&hist[a & 63u], 1u);
        if ((bq >> 6) == p10) atomicAdd(&hist[bq & 63u], 1u);
    }
    __syncthreads();
    select_bin(64, need);
    unsigned T = (p10 << 6) | sh_bin;
    unsigned nties = sh_need;
    __syncthreads();

    unsigned myt = 0;
    #pragma unroll
    for (int gg = 0; gg < 4; gg++) {
        int g = tid + gg * 256;
        if (g < C_) {
            float sum = 0.f;
            #pragma unroll
            for (int q = 0; q < 4; q++) {
                uint32_t w = k32[g * 4 + q];
                unsigned a = w & 0xFFFFu, c2 = w >> 16;
                if (a > T) sum += val16(a); else if (a == T) myt++;
                if (c2 > T) sum += val16(c2); else if (c2 == T) myt++;
            }
            cls[g] = sum;
        }
    }

    {
        unsigned v = myt;
        #pragma unroll
        for (int off = 1; off < 32; off <<= 1) {
            unsigned t = __shfl_up_sync(0xffffffffu, v, off);
            if (lane >= off) v += t;
        }
        if (lane == 31) uns[wid] = v;
        __syncthreads();
        unsigned woff = 0;
        for (int w = 0; w < wid; w++) woff += uns[w];
        unsigned rank = woff + v - myt;
        if (myt && rank < nties) {
            float vT = val16(T);
            #pragma unroll
            for (int gg = 0; gg < 4; gg++) {
                int g = tid + gg * 256;
                if (g < C_) {
                    #pragma unroll
                    for (int q = 0; q < 4; q++) {
                        uint32_t w = k32[g * 4 + q];
                        unsigned a = w & 0xFFFFu, c2 = w >> 16;
                        if (a == T) { if (rank < nties) cls[g] += vT; rank++; }
                        if (c2 == T) { if (rank < nties) cls[g] += vT; rank++; }
                    }
                }
            }
        }
    }
    __syncthreads();
    if (tid == 0) cls[tgt] += s_pos;
    __syncthreads();

    float lsum = 0.f;
    for (int c = tid; c < C_; c += 256) {
        float l = cls[c];
        if (l != 0.0f) lsum += __expf(l);
    }
    #pragma unroll
    for (int o = 16; o > 0; o >>= 1) lsum += __shfl_xor_sync(0xffffffffu, lsum, o);
    if (lane == 0) wsum[wid] = lsum;
    __syncthreads();
    if (tid == 0) {
        float tot = 0.f;
        #pragma unroll
        for (int w = 0; w < 8; w++) tot += wsum[w];
        float lt = cls[tgt];
        float num = (lt != 0.0f) ? __expf(lt) : 0.0f;
        float pr = num / (1e-8f + tot);
        atomicAdd(&g_acc[0], (double)(-__logf(pr + 1e-20f)));
    }
    __syncthreads();
    }

completion:
    if (tid == 0) {
        __threadfence();
        unsigned d = atomicAdd(&g_done, 1u);
        if (d == EPI_BLOCKS - 1) {
            double lc = g_acc[0] / (double)B_;
            double rg = g_acc[1] / (double)CN_;
            out[0] = (float)(lc + WLAMBDA * rg);
            if (out_size > 1) out[1] = (float)lc;
        }
    }
}

// ---------------- launch -----------------------------------------------------
extern "C" void kernel_launch(void* const* d_in, const int* in_sizes, int n_in,
                              void* d_out, int out_size) {
    const float* x       = (const float*)d_in[0];
    const float* proxies = (const float*)d_in[1];
    const int*   target  = (const int*)d_in[2];
    float* out = (float*)d_out;

    cudaFuncSetAttribute(gemm_all, cudaFuncAttributeMaxDynamicSharedMemorySize, DYN_SMEM);

    colnorm_kernel<<<CNP_ / 32, 256>>>(proxies);
    prep_frag<<<568, 256>>>(x, proxies);
    gemm_all<<<GRID_G, 256, DYN_SMEM>>>();
    epilogue_kernel<<<EPI_BLOCKS, 256>>>(target, out, out_size);
}

// round 17
// speedup vs baseline: 1.6230x; 1.6230x over previous
#include <cuda_runtime.h>
#include <cuda_fp16.h>
#include <math.h>
#include <stdint.h>

// ---------------- problem constants ----------------------------------------
#define B_    1024
#define DIM_  512
#define C_    1000
#define N_    8
#define CN_   8000
#define CNP_  8064
#define NEED_ 392
#define WLAMBDA 0.3
#define KS32  32        // K / 16
#define NTILES 1008
#define GRID_G 296
#define EPI_BLOCKS (B_ + (CN_ + 255) / 256)   // 1056

// ---------------- scratch -----------------------------------------------------
__device__ uint4    g_xrA[(size_t)(B_ / 16) * KS32 * 32];
__device__ uint4    g_pTA[(size_t)(CNP_ / 16) * KS32 * 32];
__device__ uint4    g_pTB[(size_t)(CNP_ / 16) * KS32 * 32];
__device__ uint4    g_ccB[(size_t)64 * KS32 * 32];
__device__ uint32_t g_simh[(size_t)B_ * (CN_ / 2)];   // fp16x2 sim
__device__ float    g_sinv[CNP_];
__device__ float    g_pmax[CN_ * 8];
__device__ float    g_psum[CN_ * 8];
__device__ float    g_diag[CN_];
__device__ double   g_acc[2];
__device__ unsigned g_done;

// ---------------- helpers ----------------------------------------------------
__device__ __forceinline__ uint32_t h2u(float a, float b) {
    __half2 h = __floats2half2_rn(a, b);
    return *(uint32_t*)&h;
}
__device__ __forceinline__ uint32_t smem_u32(const void* p) {
    uint32_t a;
    asm("{ .reg .u64 t; cvta.to.shared.u64 t, %1; cvt.u32.u64 %0, t; }" : "=r"(a) : "l"(p));
    return a;
}
__device__ __forceinline__ void cpa16(uint32_t dst, const void* src) {
    uint64_t g = __cvta_generic_to_global(src);
    asm volatile("cp.async.cg.shared.global [%0], [%1], 16;" :: "r"(dst), "l"(g));
}
#define CP_COMMIT() asm volatile("cp.async.commit_group;" ::: "memory")

__device__ __forceinline__ void mma_f16(float* c, const uint4& a, uint32_t b0, uint32_t b1) {
    asm volatile(
        "mma.sync.aligned.m16n8k16.row.col.f32.f16.f16.f32 "
        "{%0,%1,%2,%3}, {%4,%5,%6,%7}, {%8,%9}, {%0,%1,%2,%3};"
        : "+f"(c[0]), "+f"(c[1]), "+f"(c[2]), "+f"(c[3])
        : "r"(a.x), "r"(a.y), "r"(a.z), "r"(a.w), "r"(b0), "r"(b1));
}
__device__ __forceinline__ uint32_t key2_of(uint32_t w) {
    uint32_t s = (w & 0x80008000u) >> 15;
    uint32_t m = s * 0x7FFFu + 0x80008000u;
    return w ^ m;
}
__device__ __forceinline__ float val16(unsigned k) {
    unsigned short h = (k & 0x8000u) ? (unsigned short)(k ^ 0x8000u) : (unsigned short)(~k);
    return __half2float(__ushort_as_half(h));
}

// ---------------- prep 1: column inverse norms -------------------------------
__global__ void __launch_bounds__(256) colnorm_kernel(const float* __restrict__ proxies) {
    __shared__ float red[256];
    int tid = threadIdx.x;
    if (blockIdx.x == 0) {
        if (tid < 2) g_acc[tid] = 0.0;
        if (tid == 2) g_done = 0u;
    }
    int col = tid & 31, part = tid >> 5;
    int j = blockIdx.x * 32 + col;
    float acc = 0.f;
    if (j < CN_) {
        int d0 = part * 64;
        #pragma unroll 8
        for (int d = d0; d < d0 + 64; d++) {
            float v = proxies[(size_t)d * CN_ + j];
            acc += v * v;
        }
    }
    red[tid] = acc;
    __syncthreads();
    if (tid < 32) {
        float s = 0.f;
        #pragma unroll
        for (int p = 0; p < 8; p++) s += red[p * 32 + tid];
        g_sinv[j] = (j < CN_) ? (1.0f / fmaxf(sqrtf(s), 1e-12f)) : 0.f;
    }
}

// ---------------- prep 2: fragment emission (568 blocks) ----------------------
__global__ void __launch_bounds__(256) prep_frag(const float* __restrict__ x,
                                                 const float* __restrict__ proxies) {
    __shared__ __align__(16) char buf[34304];
    int tid = threadIdx.x;

    if (blockIdx.x >= 504) {
        int G = blockIdx.x - 504;
        float (*xs)[520] = (float(*)[520])buf;
        const float4* x4 = (const float4*)x;
        #pragma unroll
        for (int e = 0; e < 8; e++) {
            int lin = e * 256 + tid;
            int row = lin >> 7, kf = lin & 127;
            float4 v = x4[(size_t)(G * 16 + row) * 128 + kf];
            xs[row][kf * 4 + 0] = v.x; xs[row][kf * 4 + 1] = v.y;
            xs[row][kf * 4 + 2] = v.z; xs[row][kf * 4 + 3] = v.w;
        }
        __syncthreads();
        #pragma unroll
        for (int e = 0; e < 4; e++) {
            int lin = e * 256 + tid;
            int ks = lin >> 5, q = (lin >> 2) & 7, lc = lin & 3;
            int k0 = ks * 16 + lc * 2;
            uint4 o;
            o.x = h2u(xs[q][k0],     xs[q][k0 + 1]);
            o.y = h2u(xs[q + 8][k0], xs[q + 8][k0 + 1]);
            o.z = h2u(xs[q][k0 + 8], xs[q][k0 + 9]);
            o.w = h2u(xs[q + 8][k0 + 8], xs[q + 8][k0 + 9]);
            g_xrA[((size_t)G * KS32 + ks) * 32 + q * 4 + lc] = o;
        }
        return;
    }

    int jb = blockIdx.x >> 3, chunk = blockIdx.x & 7;
    int j0 = jb * 128, dbase = chunk * 64;
    float (*xs)[132] = (float(*)[132])buf;
    float* sinv = (float*)(buf + 33792);

    if (tid < 128) sinv[tid] = g_sinv[j0 + tid];

    #pragma unroll 4
    for (int e = 0; e < 32; e++) {
        int lin = e * 256 + tid;
        int d = lin >> 7, jj = lin & 127;
        int j = j0 + jj;
        xs[d][jj] = (j < CN_) ? proxies[(size_t)(dbase + d) * CN_ + j] : 0.f;
    }
    __syncthreads();

    #pragma unroll
    for (int e = 0; e < 4; e++) {
        int lin = e * 256 + tid;
        int g = lin >> 7, ksl = (lin >> 5) & 3, q = (lin >> 2) & 7, lc = lin & 3;
        int r0 = g * 16 + q, r1 = r0 + 8;
        float iv0 = sinv[r0], iv1 = sinv[r1];
        int dl = ksl * 16 + lc * 2;
        float v00 = xs[dl][r0] * iv0,     v01 = xs[dl + 1][r0] * iv0;
        float v10 = xs[dl][r1] * iv1,     v11 = xs[dl + 1][r1] * iv1;
        float v08 = xs[dl + 8][r0] * iv0, v09 = xs[dl + 9][r0] * iv0;
        float v18 = xs[dl + 8][r1] * iv1, v19 = xs[dl + 9][r1] * iv1;
        size_t idx = ((size_t)(j0 / 16 + g) * KS32 + chunk * 4 + ksl) * 32 + q * 4 + lc;
        uint4 oa, ob;
        oa.x = h2u(v00, v01); oa.y = h2u(v10, v11);
        oa.z = h2u(v08, v09); oa.w = h2u(v18, v19);
        ob.x = h2u(v00, v01); ob.y = h2u(v08, v09);
        ob.z = h2u(v10, v11); ob.w = h2u(v18, v19);
        g_pTA[idx] = oa;
        g_pTB[idx] = ob;
    }

    if (tid < 128) {
        int ksl = tid >> 5, qB = (tid >> 2) & 7, lc = tid & 3;
        int ca = jb * 16 + qB, cb = ca + 8;
        int dl = ksl * 16 + lc * 2;
        float a0 = 0.f, a1 = 0.f, a8 = 0.f, a9 = 0.f;
        float b0 = 0.f, b1 = 0.f, b8 = 0.f, b9 = 0.f;
        if (ca < C_) {
            #pragma unroll
            for (int n = 0; n < 8; n++) {
                int jl = qB * 8 + n;
                float iv = sinv[jl];
                a0 += xs[dl][jl] * iv;     a1 += xs[dl + 1][jl] * iv;
                a8 += xs[dl + 8][jl] * iv; a9 += xs[dl + 9][jl] * iv;
            }
        }
        if (cb < C_) {
            #pragma unroll
            for (int n = 0; n < 8; n++) {
                int jl = 64 + qB * 8 + n;
                float iv = sinv[jl];
                b0 += xs[dl][jl] * iv;     b1 += xs[dl + 1][jl] * iv;
                b8 += xs[dl + 8][jl] * iv; b9 += xs[dl + 9][jl] * iv;
            }
        }
        uint4 o;
        o.x = h2u(a0, a1);
        o.y = h2u(a8, a9);
        o.z = h2u(b0, b1);
        o.w = h2u(b8, b9);
        g_ccB[((size_t)jb * KS32 + chunk * 4 + ksl) * 32 + qB * 4 + lc] = o;
    }
}

// ---------------- fp16 GEMM: 6-stage x 16KB (K=32 chunks), 2 CTA/SM ----------
#define NCHUNK 16
#define SSTG 16384
#define DYN_SMEM (6 * SSTG)   // 98304
#define TP 130

__device__ __forceinline__ void tile_coords(int bid, const uint4*& Ag, const uint4*& Bg,
                                            int& bm, int& bn, bool& mode1) {
    mode1 = (bid >= 504);
    if (!mode1) {
        Ag = g_xrA; Bg = g_pTB;
        bn = (bid % 63) * 128; bm = (bid / 63) * 128;
    } else {
        int b2 = bid - 504;
        Ag = g_pTA; Bg = g_ccB;
        bn = (b2 & 7) * 128; bm = (b2 >> 3) * 128;
    }
}

// one K=32 chunk: A 8KB + B 8KB
__device__ __forceinline__ void load_stage_g(uint32_t sb, int tid, const uint4* Ag,
                                             const uint4* Bg, int GA0, int GB0,
                                             int ch, int s) {
    uint32_t stage = sb + (uint32_t)s * SSTG;
    #pragma unroll
    for (int e = 0; e < 4; e++) {
        int lin = e * 256 + tid;
        if (lin < 512) {
            int ks = lin >> 8, g = (lin >> 5) & 7, q = (lin >> 2) & 7, lc = lin & 3;
            cpa16(stage + (uint32_t)lin * 16,
                  Ag + ((size_t)(GA0 + g) * KS32 + ch * 2 + ks) * 32 + q * 4 + lc);
        } else {
            int l2 = lin - 512;
            int ks = l2 >> 8, gB = (l2 >> 5) & 7, qB = (l2 >> 2) & 7, lc = l2 & 3;
            cpa16(stage + 8192u + (uint32_t)l2 * 16,
                  Bg + ((size_t)(GB0 + gB) * KS32 + ch * 2 + ks) * 32 + qB * 4 + lc);
        }
    }
    CP_COMMIT();
}

__global__ void __launch_bounds__(256, 2) gemm_all() {
    extern __shared__ char sh[];
    int tid = threadIdx.x, wid = tid >> 5, lane = tid & 31;
    int lr = lane >> 2, lc4 = lane & 3;
    uint32_t sb = smem_u32(sh);
    int ga = (wid >> 2) * 4;
    int gb2 = (wid & 3) * 2;
    int wm = (wid >> 2) * 64, wn = (wid & 3) * 32;
    bool preloaded = false;

    for (int t = 0; t < 4; t++) {
        int bid = (int)blockIdx.x + t * GRID_G;
        if (bid >= NTILES) break;

        const uint4 *Ag, *Bg;
        int bm, bn;
        bool mode1;
        tile_coords(bid, Ag, Bg, bm, bn, mode1);
        int GA0 = bm / 16, GB0 = bn / 16;

        if (!preloaded) {
            #pragma unroll
            for (int p = 0; p < 5; p++)
                load_stage_g(sb, tid, Ag, Bg, GA0, GB0, p, p);
        }

        float c[4][4][4];
        #pragma unroll
        for (int mt = 0; mt < 4; mt++)
            #pragma unroll
            for (int nt = 0; nt < 4; nt++)
                #pragma unroll
                for (int i = 0; i < 4; i++) c[mt][nt][i] = 0.f;

        for (int ch = 0; ch < NCHUNK; ch++) {
            if (ch <= NCHUNK - 5)      asm volatile("cp.async.wait_group 4;" ::: "memory");
            else if (ch == NCHUNK - 4) asm volatile("cp.async.wait_group 3;" ::: "memory");
            else if (ch == NCHUNK - 3) asm volatile("cp.async.wait_group 2;" ::: "memory");
            else if (ch == NCHUNK - 2) asm volatile("cp.async.wait_group 1;" ::: "memory");
            else                       asm volatile("cp.async.wait_group 0;" ::: "memory");
            __syncthreads();

            if (ch + 5 < NCHUNK) load_stage_g(sb, tid, Ag, Bg, GA0, GB0, ch + 5, (ch + 5) % 6);

            const uint4* As = (const uint4*)(sh + (ch % 6) * SSTG);
            const uint4* Bs = As + 512;

            #pragma unroll
            for (int ks = 0; ks < 2; ks++) {
                uint4 va[4], vb[2];
                #pragma unroll
                for (int mt = 0; mt < 4; mt++)
                    va[mt] = As[((ks * 8 + ga + mt) * 8 + lr) * 4 + lc4];
                #pragma unroll
                for (int u = 0; u < 2; u++)
                    vb[u] = Bs[((ks * 8 + gb2 + u) * 8 + lr) * 4 + lc4];
                #pragma unroll
                for (int mt = 0; mt < 4; mt++) {
                    mma_f16(c[mt][0], va[mt], vb[0].x, vb[0].y);
                    mma_f16(c[mt][1], va[mt], vb[0].z, vb[0].w);
                    mma_f16(c[mt][2], va[mt], vb[1].x, vb[1].y);
                    mma_f16(c[mt][3], va[mt], vb[1].z, vb[1].w);
                }
            }
        }
        __syncthreads();   // all MMAs done; buffers free

        preloaded = false;
        if (!mode1) {
            int nbid = (int)blockIdx.x + (t + 1) * GRID_G;
            if (nbid < NTILES) {
                const uint4 *Ag2, *Bg2;
                int bm2, bn2;
                bool m1n;
                tile_coords(nbid, Ag2, Bg2, bm2, bn2, m1n);
                #pragma unroll
                for (int p = 0; p < 5; p++)
                    load_stage_g(sb, tid, Ag2, Bg2, bm2 / 16, bn2 / 16, p, p);
                preloaded = true;
            }
            #pragma unroll
            for (int mt = 0; mt < 4; mt++) {
                int row = bm + wm + mt * 16 + lr;
                #pragma unroll
                for (int nt = 0; nt < 4; nt++) {
                    int col = bn + wn + nt * 8 + lc4 * 2;
                    if (col < CN_) {
                        g_simh[(size_t)row * (CN_ / 2) + (col >> 1)] = h2u(c[mt][nt][0], c[mt][nt][1]);
                        g_simh[(size_t)(row + 8) * (CN_ / 2) + (col >> 1)] = h2u(c[mt][nt][2], c[mt][nt][3]);
                    }
                }
            }
            continue;
        }

        // mode 1: smem tile dump (128 x 130 floats = 66560 B <= 98304) + lse
        float* tile = (float*)sh;
        #pragma unroll
        for (int mt = 0; mt < 4; mt++) {
            int r0 = wm + mt * 16 + lr;
            #pragma unroll
            for (int nt = 0; nt < 4; nt++) {
                int cc = wn + nt * 8 + lc4 * 2;
                *(float2*)&tile[r0 * TP + cc] = make_float2(c[mt][nt][0], c[mt][nt][1]);
                *(float2*)&tile[(r0 + 8) * TP + cc] = make_float2(c[mt][nt][2], c[mt][nt][3]);
            }
        }
        __syncthreads();

        {
            int r = tid >> 1, h = tid & 1;
            int gr = bm + r;
            int vcols = C_ - bn; if (vcols > 128) vcols = 128;
            int cA = h * 64;
            int cB = cA + 64; if (cB > vcols) cB = vcols;
            float m = -3.0e38f;
            for (int j = cA; j < cB; j++) m = fmaxf(m, tile[r * TP + j]);
            float s = 0.f;
            for (int j = cA; j < cB; j++) s += __expf(tile[r * TP + j] - m);
            float mo = __shfl_xor_sync(0xffffffffu, m, 1);
            float so = __shfl_xor_sync(0xffffffffu, s, 1);
            float M = fmaxf(m, mo);
            float S = s * __expf(m - M) + so * __expf(mo - M);
            if (h == 0 && gr < CN_) {
                g_pmax[gr * 8 + (bn >> 7)] = M;
                g_psum[gr * 8 + (bn >> 7)] = S;
                int cl = gr >> 3;
                if (cl >= bn && cl - bn < vcols) g_diag[gr] = tile[r * TP + (cl - bn)];
            }
        }
        __syncthreads();
    }
}

// ---------------- epilogue: topk+loss, lse combine, inline finalize ----------
__global__ void __launch_bounds__(256) epilogue_kernel(const int* __restrict__ target,
                                                       float* out, int out_size) {
    __shared__ unsigned short key16[CN_];
    __shared__ unsigned hist[1024];
    __shared__ float    cls[C_];
    __shared__ unsigned uns[8];
    __shared__ float    wsum[8];
    __shared__ float    s_pos;
    __shared__ unsigned sh_bin, sh_need;

    int tid = threadIdx.x;
    int wid = tid >> 5, lane = tid & 31;

    if (blockIdx.x >= B_) {
        int row = (int)(blockIdx.x - B_) * 256 + tid;
        float regv = 0.f;
        if (row < CN_) {
            float M = -3.0e38f;
            #pragma unroll
            for (int t = 0; t < 8; t++) M = fmaxf(M, g_pmax[row * 8 + t]);
            float S = 0.f;
            #pragma unroll
            for (int t = 0; t < 8; t++)
                S += g_psum[row * 8 + t] * __expf(g_pmax[row * 8 + t] - M);
            regv = M + __logf(S) - g_diag[row];
        }
        #pragma unroll
        for (int o = 16; o > 0; o >>= 1) regv += __shfl_xor_sync(0xffffffffu, regv, o);
        if (lane == 0 && regv != 0.f) atomicAdd(&g_acc[1], (double)regv);
        __syncthreads();
        goto completion;
    }

    {
    int b = blockIdx.x;
    int tgt = target[b];
    const uint4* rowh = (const uint4*)(g_simh + (size_t)b * (CN_ / 2));
    uint32_t* k32 = (uint32_t*)key16;

    for (int i = tid; i < 1024; i += 256) hist[i] = 0;
    if (tid == 0) s_pos = 0.f;
    __syncthreads();

    float pos = 0.f;
    for (int g = tid; g < C_; g += 256) {
        uint4 w = rowh[g];
        if (g == tgt) {
            float2 f0 = __half22float2(*(__half2*)&w.x);
            float2 f1 = __half22float2(*(__half2*)&w.y);
            float2 f2 = __half22float2(*(__half2*)&w.z);
            float2 f3 = __half22float2(*(__half2*)&w.w);
            pos = f0.x + f0.y + f1.x + f1.y + f2.x + f2.y + f3.x + f3.y;
            *(uint4*)&k32[g * 4] = make_uint4(0, 0, 0, 0);
        } else {
            uint32_t k0 = key2_of(w.x), k1 = key2_of(w.y), k2 = key2_of(w.z), k3 = key2_of(w.w);
            *(uint4*)&k32[g * 4] = make_uint4(k0, k1, k2, k3);
            atomicAdd(&hist[(k0 & 0xFFFFu) >> 6], 1u);
            atomicAdd(&hist[k0 >> 22], 1u);
            atomicAdd(&hist[(k1 & 0xFFFFu) >> 6], 1u);
            atomicAdd(&hist[k1 >> 22], 1u);
            atomicAdd(&hist[(k2 & 0xFFFFu) >> 6], 1u);
            atomicAdd(&hist[k2 >> 22], 1u);
            atomicAdd(&hist[(k3 & 0xFFFFu) >> 6], 1u);
            atomicAdd(&hist[k3 >> 22], 1u);
        }
    }
    if (pos != 0.f) atomicAdd(&s_pos, pos);
    __syncthreads();

    auto select_bin = [&](int nb, unsigned nd) {
        int nch = nb >> 3;
        unsigned chunk = 0;
        if (tid < nch) {
            int base = tid * 8;
            #pragma unroll
            for (int i = 0; i < 8; i++) chunk += hist[base + i];
        }
        unsigned v = chunk;
        #pragma unroll
        for (int off = 1; off < 32; off <<= 1) {
            unsigned t = __shfl_down_sync(0xffffffffu, v, off);
            if (lane + off < 32) v += t;
        }
        if (lane == 0) uns[wid] = v;
        __syncthreads();
        unsigned woff = 0;
        for (int w = wid + 1; w < 8; w++) woff += uns[w];
        unsigned Sincl = v + woff;
        unsigned Saft = Sincl - chunk;
        if (tid < nch && Saft < nd && Sincl >= nd) {
            unsigned cum = Saft;
            int bb = tid * 8 + 7;
            while (cum + hist[bb] < nd) { cum += hist[bb]; bb--; }
            sh_bin = (unsigned)bb;
            sh_need = nd - cum;
        }
        __syncthreads();
    };

    select_bin(1024, NEED_);
    unsigned p10 = sh_bin;
    unsigned need = sh_need;
    __syncthreads();

    for (int i = tid; i < 64; i += 256) hist[i] = 0;
    __syncthreads();
    for (int t = tid; t < CN_ / 2; t += 256) {
        uint32_t w = k32[t];
        unsigned a = w & 0xFFFFu, bq = w >> 16;
        if ((a >> 6) == p10) atomicAdd(&hist[a & 63u], 1u);
        if ((bq >> 6) == p10) atomicAdd(&hist[bq & 63u], 1u);
    }
    __syncthreads();
    select_bin(64, need);
    unsigned T = (p10 << 6) | sh_bin;
    unsigned nties = sh_need;
    __syncthreads();

    unsigned myt = 0;
    #pragma unroll
    for (int gg = 0; gg < 4; gg++) {
        int g = tid + gg * 256;
        if (g < C_) {
            float sum = 0.f;
            #pragma unroll
            for (int q = 0; q < 4; q++) {
                uint32_t w = k32[g * 4 + q];
                unsigned a = w & 0xFFFFu, c2 = w >> 16;
                if (a > T) sum += val16(a); else if (a == T) myt++;
                if (c2 > T) sum += val16(c2); else if (c2 == T) myt++;
            }
            cls[g] = sum;
        }
    }

    {
        unsigned v = myt;
        #pragma unroll
        for (int off = 1; off < 32; off <<= 1) {
            unsigned t = __shfl_up_sync(0xffffffffu, v, off);
            if (lane >= off) v += t;
        }
        if (lane == 31) uns[wid] = v;
        __syncthreads();
        unsigned woff = 0;
        for (int w = 0; w < wid; w++) woff += uns[w];
        unsigned rank = woff + v - myt;
        if (myt && rank < nties) {
            float vT = val16(T);
            #pragma unroll
            for (int gg = 0; gg < 4; gg++) {
                int g = tid + gg * 256;
                if (g < C_) {
                    #pragma unroll
                    for (int q = 0; q < 4; q++) {
                        uint32_t w = k32[g * 4 + q];
                        unsigned a = w & 0xFFFFu, c2 = w >> 16;
                        if (a == T) { if (rank < nties) cls[g] += vT; rank++; }
                        if (c2 == T) { if (rank < nties) cls[g] += vT; rank++; }
                    }
                }
            }
        }
    }
    __syncthreads();
    if (tid == 0) cls[tgt] += s_pos;
    __syncthreads();

    float lsum = 0.f;
    for (int c = tid; c < C_; c += 256) {
        float l = cls[c];
        if (l != 0.0f) lsum += __expf(l);
    }
    #pragma unroll
    for (int o = 16; o > 0; o >>= 1) lsum += __shfl_xor_sync(0xffffffffu, lsum, o);
    if (lane == 0) wsum[wid] = lsum;
    __syncthreads();
    if (tid == 0) {
        float tot = 0.f;
        #pragma unroll
        for (int w = 0; w < 8; w++) tot += wsum[w];
        float lt = cls[tgt];
        float num = (lt != 0.0f) ? __expf(lt) : 0.0f;
        float pr = num / (1e-8f + tot);
        atomicAdd(&g_acc[0], (double)(-__logf(pr + 1e-20f)));
    }
    __syncthreads();
    }

completion:
    if (tid == 0) {
        __threadfence();
        unsigned d = atomicAdd(&g_done, 1u);
        if (d == EPI_BLOCKS - 1) {
            double lc = g_acc[0] / (double)B_;
            double rg = g_acc[1] / (double)CN_;
            out[0] = (float)(lc + WLAMBDA * rg);
            if (out_size > 1) out[1] = (float)lc;
        }
    }
}

// ---------------- launch -----------------------------------------------------
extern "C" void kernel_launch(void* const* d_in, const int* in_sizes, int n_in,
                              void* d_out, int out_size) {
    const float* x       = (const float*)d_in[0];
    const float* proxies = (const float*)d_in[1];
    const int*   target  = (const int*)d_in[2];
    float* out = (float*)d_out;

    cudaFuncSetAttribute(gemm_all, cudaFuncAttributeMaxDynamicSharedMemorySize, DYN_SMEM);

    colnorm_kernel<<<CNP_ / 32, 256>>>(proxies);
    prep_frag<<<568, 256>>>(x, proxies);
    gemm_all<<<GRID_G, 256, DYN_SMEM>>>();
    epilogue_kernel<<<EPI_BLOCKS, 256>>>(target, out, out_size);
}